// round 5
// baseline (speedup 1.0000x reference)
#include <cuda_runtime.h>

#define DIM 16

// Folded weights: out = chem @ M^T + c, where M = Wo @ Wv, c = Wo @ bv + bo
__device__ __align__(16) float g_M[DIM * DIM];  // M[j][i], row-major
__device__ __align__(16) float g_c[DIM];

// ---------------------------------------------------------------------------
// Tiny prep kernel: fold the two 16x16 matmuls + biases into one matrix.
// One block, 256 threads: thread (j,i) computes M[j][i].
// ---------------------------------------------------------------------------
__global__ void prep_kernel(const float* __restrict__ in_w,   // [48,16] (Wq|Wk|Wv)
                            const float* __restrict__ in_b,   // [48]
                            const float* __restrict__ out_w,  // [16,16]
                            const float* __restrict__ out_b)  // [16]
{
    const int t = threadIdx.x;           // 0..255
    const int j = t >> 4;
    const int i = t & 15;
    float s = 0.f;
#pragma unroll
    for (int k = 0; k < DIM; ++k)
        s += out_w[j * DIM + k] * in_w[(2 * DIM + k) * DIM + i];
    g_M[j * DIM + i] = s;
    if (i == 0) {
        float c = out_b[j];
#pragma unroll
        for (int k = 0; k < DIM; ++k)
            c += out_w[j * DIM + k] * in_b[2 * DIM + k];
        g_c[j] = c;
    }
}

// packed f32x2 FMA (Blackwell; only reachable via PTX)
__device__ __forceinline__ unsigned long long ffma2(unsigned long long a,
                                                    unsigned long long b,
                                                    unsigned long long c)
{
    unsigned long long d;
    asm("fma.rn.f32x2 %0, %1, %2, %3;" : "=l"(d) : "l"(a), "l"(b), "l"(c));
    return d;
}

// ---------------------------------------------------------------------------
// Main kernel: 4 threads per row, each computes 4 output columns.
// Weights live in registers as packed f32x2 pairs (reused across the
// grid-stride loop), inputs load as ulonglong2 (pairs pre-packed).
// ---------------------------------------------------------------------------
__global__ void __launch_bounds__(256)
matvec_kernel(const float* __restrict__ chem, float* __restrict__ out, int rows)
{
    const int g       = blockIdx.x * blockDim.x + threadIdx.x;
    const int quarter = g & 3;            // which 4-column group of the row
    const int jg      = quarter * 4;      // first output column
    const int row0    = g >> 2;
    const int rstride = (gridDim.x * blockDim.x) >> 2;

    // Load this thread's 4 rows of M (64 weights) as 32 packed f32x2 regs.
    unsigned long long w[4][8];
    float c[4];
#pragma unroll
    for (int j = 0; j < 4; ++j) {
        const unsigned long long* wp =
            reinterpret_cast<const unsigned long long*>(&g_M[(jg + j) * DIM]);
#pragma unroll
        for (int i2 = 0; i2 < 8; ++i2) w[j][i2] = wp[i2];
        c[j] = g_c[jg + j];
    }

    for (int r = row0; r < rows; r += rstride) {
        const ulonglong2* p =
            reinterpret_cast<const ulonglong2*>(chem + (size_t)r * DIM);
        ulonglong2 a0 = p[0];
        ulonglong2 a1 = p[1];
        ulonglong2 a2 = p[2];
        ulonglong2 a3 = p[3];
        unsigned long long ap[8] = {a0.x, a0.y, a1.x, a1.y,
                                    a2.x, a2.y, a3.x, a3.y};

        float4 res;
        float* rp = reinterpret_cast<float*>(&res);
#pragma unroll
        for (int j = 0; j < 4; ++j) {
            // acc = (c[j], 0) packed; lanewise FMA over 8 input pairs
            unsigned long long acc =
                (unsigned long long)__float_as_uint(c[j]);
#pragma unroll
            for (int i2 = 0; i2 < 8; ++i2)
                acc = ffma2(ap[i2], w[j][i2], acc);
            const float lo = __uint_as_float((unsigned int)acc);
            const float hi = __uint_as_float((unsigned int)(acc >> 32));
            rp[j] = lo + hi;
        }

        // one coalesced 16B store per thread; 4 threads cover the row
        float4* op = reinterpret_cast<float4*>(out + (size_t)r * DIM);
        op[quarter] = res;
    }
}

extern "C" void kernel_launch(void* const* d_in, const int* in_sizes, int n_in,
                              void* d_out, int out_size)
{
    // inputs: 0=fp_16 (UNUSED), 1=chem_16, 2=in_proj_weight, 3=in_proj_bias,
    //         4=out_proj_weight, 5=out_proj_bias
    const float* chem  = (const float*)d_in[1];
    const float* in_w  = (const float*)d_in[2];
    const float* in_b  = (const float*)d_in[3];
    const float* out_w = (const float*)d_in[4];
    const float* out_b = (const float*)d_in[5];
    float* out = (float*)d_out;

    const int rows = in_sizes[1] / DIM;   // 2,097,152

    prep_kernel<<<1, 256>>>(in_w, in_b, out_w, out_b);

    // 2048 blocks x 256 threads = 2^19 threads -> 2^17 rows/iter -> 16 iters
    int blocks = 2048;
    long long need = ((long long)rows * 4 + 255) / 256;
    if (need < blocks) blocks = (int)need;
    matvec_kernel<<<blocks, 256>>>(chem, out, rows);
}